// round 14
// baseline (speedup 1.0000x reference)
#include <cuda_runtime.h>
#include <cuda_fp16.h>
#include <cstdint>
#include <math.h>

// Problem constants
#define BATCH   2
#define TSEQ    2048
#define EMBED   1024
#define NHEAD   16
#define HDIM    64
#define MTOK    (BATCH * TSEQ)        // 4096
#define QKVCOLS (3 * EMBED)           // 3072

// Scratch (allocation-free rule: __device__ globals)
__device__ __half g_xa_hi[(size_t)MTOK * EMBED];    // x split / attn out split (hi)
__device__ __half g_xa_lo[(size_t)MTOK * EMBED];    // (lo)
__device__ __half g_wq[(size_t)QKVCOLS * EMBED];    // w_qkv^T [3072][1024] fp16
__device__ __half g_wo[(size_t)EMBED * EMBED];      // w_out^T [1024][1024] fp16
// per-head qkv: [b][h][t][64]
__device__ __half g_qh[(size_t)MTOK * EMBED];
__device__ __half g_ql[(size_t)MTOK * EMBED];
__device__ __half g_kh[(size_t)MTOK * EMBED];
__device__ __half g_vh[(size_t)MTOK * EMBED];

// ---------------------------------------------------------------------------
// PTX helpers (plain sm_80+ PTX)
// ---------------------------------------------------------------------------
__device__ __forceinline__ uint32_t smem_u32(const void* p) {
    uint32_t a;
    asm("{ .reg .u64 t; cvta.to.shared.u64 t, %1; cvt.u32.u64 %0, t; }"
        : "=r"(a) : "l"(p));
    return a;
}

#define CP_ASYNC16(dst, src) \
    asm volatile("cp.async.cg.shared.global [%0], [%1], 16;" :: "r"(dst), "l"(src))
#define CP_COMMIT()  asm volatile("cp.async.commit_group;" ::: "memory")
#define CP_WAIT0()   asm volatile("cp.async.wait_group 0;" ::: "memory")

#define LDSM_X4(r0, r1, r2, r3, a) \
    asm volatile("ldmatrix.sync.aligned.m8n8.x4.shared.b16 {%0,%1,%2,%3}, [%4];" \
                 : "=r"(r0), "=r"(r1), "=r"(r2), "=r"(r3) : "r"(a))
#define LDSM_X4_T(r0, r1, r2, r3, a) \
    asm volatile("ldmatrix.sync.aligned.m8n8.x4.trans.shared.b16 {%0,%1,%2,%3}, [%4];" \
                 : "=r"(r0), "=r"(r1), "=r"(r2), "=r"(r3) : "r"(a))

__device__ __forceinline__ void mma16816(float* d, const uint32_t* a,
                                         uint32_t b0, uint32_t b1) {
    asm volatile(
        "mma.sync.aligned.m16n8k16.row.col.f32.f16.f16.f32 "
        "{%0,%1,%2,%3}, {%4,%5,%6,%7}, {%8,%9}, {%0,%1,%2,%3};"
        : "+f"(d[0]), "+f"(d[1]), "+f"(d[2]), "+f"(d[3])
        : "r"(a[0]), "r"(a[1]), "r"(a[2]), "r"(a[3]), "r"(b0), "r"(b1));
}

__device__ __forceinline__ uint32_t swz(uint32_t o) {
    return o ^ ((o >> 3) & 0x70);
}

// Split pair of floats into packed fp16 hi + fp16 lo residual
__device__ __forceinline__ void split2h(float a, float b, uint32_t& h, uint32_t& l) {
    __half ha = __float2half(a), hb = __float2half(b);
    float ra = a - __half2float(ha);
    float rb = b - __half2float(hb);
    __half2 H = __halves2half2(ha, hb);
    __half2 L = __halves2half2(__float2half(ra), __float2half(rb));
    h = *(uint32_t*)&H;
    l = *(uint32_t*)&L;
}
// Pack pair of floats to fp16x2 (round-to-nearest)
__device__ __forceinline__ uint32_t pack2h(float a, float b) {
    __half2 H = __halves2half2(__float2half(a), __float2half(b));
    return *(uint32_t*)&H;
}

// ---------------------------------------------------------------------------
// Fused prep (single launch, 3 sections):
//  [0, 4096)       : split x fp32 -> fp16 hi/lo
//  [4096, 7168)    : transpose+convert w_qkv -> [3072][1024] fp16
//  [7168, 8192)    : transpose+convert w_out -> [1024][1024] fp16
// ---------------------------------------------------------------------------
#define PREP_SPLIT_BLOCKS 4096
#define PREP_WQ_BLOCKS    3072   // (3072/32) x (1024/32)
#define PREP_WO_BLOCKS    1024   // (1024/32) x (1024/32)
#define PREP_BLOCKS (PREP_SPLIT_BLOCKS + PREP_WQ_BLOCKS + PREP_WO_BLOCKS)

__device__ __forceinline__ void wconv_tile(
    const float* __restrict__ W, __half* __restrict__ T,
    int K, int N, int n0, int k0, int tid, float* t /*[32][33]*/)
{
    int tx = tid & 31, ty = tid >> 5;            // 32 x 8
    #pragma unroll
    for (int i = 0; i < 4; i++)
        t[(ty + i * 8) * 33 + tx] = W[(size_t)(k0 + ty + i * 8) * N + n0 + tx];
    __syncthreads();
    #pragma unroll
    for (int i = 0; i < 4; i++) {
        float v = t[tx * 33 + ty + i * 8];
        T[(size_t)(n0 + ty + i * 8) * K + k0 + tx] = __float2half(v);
    }
}

__global__ __launch_bounds__(256) void prep_kernel(
    const float* __restrict__ x, const float* __restrict__ w_qkv,
    const float* __restrict__ w_out,
    __half* __restrict__ xa_hi, __half* __restrict__ xa_lo,
    __half* __restrict__ wq, __half* __restrict__ wo)
{
    __shared__ float t[32 * 33];
    const int bid = blockIdx.x;
    const int tid = threadIdx.x;

    if (bid < PREP_SPLIT_BLOCKS) {
        int i = bid * 256 + tid;                 // < 1048576 = n4
        float4 v = ((const float4*)x)[i];
        uint32_t h0, l0, h1, l1;
        split2h(v.x, v.y, h0, l0);
        split2h(v.z, v.w, h1, l1);
        uint32_t* hp = (uint32_t*)xa_hi;
        uint32_t* lp = (uint32_t*)xa_lo;
        hp[2*i] = h0; hp[2*i+1] = h1;
        lp[2*i] = l0; lp[2*i+1] = l1;
    } else if (bid < PREP_SPLIT_BLOCKS + PREP_WQ_BLOCKS) {
        int b2 = bid - PREP_SPLIT_BLOCKS;
        int n0 = (b2 % 96) * 32;                 // QKVCOLS/32 = 96
        int k0 = (b2 / 96) * 32;
        wconv_tile(w_qkv, wq, EMBED, QKVCOLS, n0, k0, tid, t);
    } else {
        int b2 = bid - PREP_SPLIT_BLOCKS - PREP_WQ_BLOCKS;
        int n0 = (b2 % 32) * 32;
        int k0 = (b2 / 32) * 32;
        wconv_tile(w_out, wo, EMBED, EMBED, n0, k0, tid, t);
    }
}

// ---------------------------------------------------------------------------
// Warp-mma GEMM (fp16 2-term): C = (Ahi+Alo)[M,1024] @ (B[N,1024])^T + bias
// 128x128 CTA tile, 256 threads = 8 warps (4m x 2n), 32x64 per warp.
// K chunk = 64 fp16, double-buffered cp.async (96KB smem -> 2 CTAs/SM).
// MODE 0: fp32 C output.  MODE 1: QKV epilogue (scale+split q; fp16 k, v)
// ---------------------------------------------------------------------------
#define GK      1024
#define NCHUNK  16
#define TILE_B  16384
#define BUF_B   (3 * TILE_B)        // Ah, Al, Bh
#define GEMM_SMEM (2 * BUF_B)       // 98304

__device__ __forceinline__ void load_chunk_async(
    const __half* __restrict__ Ahi, const __half* __restrict__ Alo,
    const __half* __restrict__ Bh,
    int bm, int bn, int kbyte, uint32_t buf, int tid)
{
    #pragma unroll
    for (int i = 0; i < 4; i++) {
        int idx = tid + i * 256;                  // 0..1023
        int r   = idx >> 3;                       // 0..127
        int cb  = (idx & 7) * 16;
        uint32_t so = swz((uint32_t)(r * 128 + cb));
        const char* gA = (const char*)(Ahi + (size_t)(bm + r) * GK) + kbyte + cb;
        const char* gAl= (const char*)(Alo + (size_t)(bm + r) * GK) + kbyte + cb;
        const char* gB = (const char*)(Bh  + (size_t)(bn + r) * GK) + kbyte + cb;
        CP_ASYNC16(buf + so,              gA);
        CP_ASYNC16(buf + TILE_B + so,     gAl);
        CP_ASYNC16(buf + 2 * TILE_B + so, gB);
    }
}

template <int MODE>
__global__ __launch_bounds__(256, 2) void gemm_mma_kernel(
    const __half* __restrict__ Ahi, const __half* __restrict__ Alo,
    const __half* __restrict__ Bh,
    const float* __restrict__ bias, float* __restrict__ C, int N,
    __half* __restrict__ qh, __half* __restrict__ ql,
    __half* __restrict__ kh, __half* __restrict__ vh)
{
    extern __shared__ char smem[];
    const uint32_t sb = smem_u32(smem);
    const int tid = threadIdx.x;
    const int wid = tid >> 5;
    const int lid = tid & 31;
    const int wm  = wid >> 1;       // 0..3 -> m offset wm*32
    const int wn  = wid & 1;        // 0..1 -> n offset wn*64

    const int bm = blockIdx.y * 128;
    const int bn = blockIdx.x * 128;

    float acc[2][8][4];
    #pragma unroll
    for (int a = 0; a < 2; a++)
        #pragma unroll
        for (int j = 0; j < 8; j++)
            #pragma unroll
            for (int k = 0; k < 4; k++) acc[a][j][k] = 0.0f;

    uint32_t aob[2];
    #pragma unroll
    for (int mf = 0; mf < 2; mf++)
        aob[mf] = (uint32_t)((wm * 32 + mf * 16 + (lid & 15)) * 128 + ((lid >> 4) << 4));
    uint32_t bob = (uint32_t)((wn * 64 + ((lid >> 4) << 3) + (lid & 7)) * 128
                              + (((lid >> 3) & 1) << 4));

    load_chunk_async(Ahi, Alo, Bh, bm, bn, 0, sb, tid);
    CP_COMMIT();
    CP_WAIT0();
    __syncthreads();

    for (int c = 0; c < NCHUNK; c++) {
        const uint32_t buf = sb + (c & 1) * BUF_B;
        if (c + 1 < NCHUNK) {
            load_chunk_async(Ahi, Alo, Bh, bm, bn, (c + 1) * 128,
                             sb + ((c + 1) & 1) * BUF_B, tid);
            CP_COMMIT();
        }

        const uint32_t Ah_b = buf;
        const uint32_t Al_b = buf + TILE_B;
        const uint32_t Bh_b = buf + 2 * TILE_B;

        #pragma unroll
        for (int ks = 0; ks < 4; ks++) {
            const uint32_t ko = (uint32_t)(ks * 32);
            uint32_t ah[2][4], al[2][4];
            #pragma unroll
            for (int mf = 0; mf < 2; mf++) {
                uint32_t ao = swz(aob[mf] + ko);
                LDSM_X4(ah[mf][0], ah[mf][1], ah[mf][2], ah[mf][3], Ah_b + ao);
                LDSM_X4(al[mf][0], al[mf][1], al[mf][2], al[mf][3], Al_b + ao);
            }
            #pragma unroll
            for (int jg = 0; jg < 4; jg++) {
                uint32_t bo = swz(bob + (uint32_t)(jg * 2048) + ko);
                uint32_t b0, b1, b2, b3;
                LDSM_X4(b0, b1, b2, b3, Bh_b + bo);
                const int j0 = jg * 2, j1 = jg * 2 + 1;
                #pragma unroll
                for (int mf = 0; mf < 2; mf++) {
                    mma16816(acc[mf][j0], ah[mf], b0, b1);
                    mma16816(acc[mf][j1], ah[mf], b2, b3);
                    mma16816(acc[mf][j0], al[mf], b0, b1);
                    mma16816(acc[mf][j1], al[mf], b2, b3);
                }
            }
        }

        if (c + 1 < NCHUNK) {
            CP_WAIT0();
            __syncthreads();
        }
    }

    const int rbase = bm + wm * 32 + (lid >> 2);
    const int cbase = bn + wn * 64 + (lid & 3) * 2;

    if (MODE == 0) {
        #pragma unroll
        for (int j = 0; j < 8; j++) {
            const int col = cbase + j * 8;
            float2 bb = *(const float2*)&bias[col];
            #pragma unroll
            for (int mf = 0; mf < 2; mf++) {
                int r0 = rbase + mf * 16;
                float2 v0, v1;
                v0.x = acc[mf][j][0] + bb.x;
                v0.y = acc[mf][j][1] + bb.y;
                v1.x = acc[mf][j][2] + bb.x;
                v1.y = acc[mf][j][3] + bb.y;
                *(float2*)&C[(size_t)r0 * N + col]       = v0;
                *(float2*)&C[(size_t)(r0 + 8) * N + col] = v1;
            }
        }
    } else {
        // QKV epilogue: bias; q scaled 0.125 + split hi/lo; k,v single fp16
        #pragma unroll
        for (int j = 0; j < 8; j++) {
            const int col = cbase + j * 8;
            float2 bb = *(const float2*)&bias[col];
            const int sec = col >> 10;
            const int rr  = col & 1023;
            const int hh  = rr >> 6;
            const int dd  = rr & 63;
            #pragma unroll
            for (int mf = 0; mf < 2; mf++) {
                #pragma unroll
                for (int half = 0; half < 2; half++) {
                    int row = rbase + mf * 16 + half * 8;
                    float a0 = acc[mf][j][half*2+0] + bb.x;
                    float a1 = acc[mf][j][half*2+1] + bb.y;
                    int bb_ = row >> 11, tt = row & 2047;
                    size_t off = (((size_t)(bb_ * NHEAD + hh)) * TSEQ + tt) * HDIM + dd;
                    if (sec == 0) {
                        uint32_t H, L;
                        split2h(a0 * 0.125f, a1 * 0.125f, H, L);
                        *(uint32_t*)(qh + off) = H;
                        *(uint32_t*)(ql + off) = L;
                    } else if (sec == 1) {
                        *(uint32_t*)(kh + off) = pack2h(a0, a1);
                    } else {
                        *(uint32_t*)(vh + off) = pack2h(a0, a1);
                    }
                }
            }
        }
    }
}

// ---------------------------------------------------------------------------
// Tensor-core flash attention (fp16 2-term, causal).
// Grid: (NHEAD, BATCH, TSEQ/128) with qt = gridDim.z-1-blockIdx.z (LPT:
// heaviest q-tiles launch first — work per CTA is 2*qt+2 KV tiles and the
// kernel is 1 CTA/SM, so descending-work launch order minimizes makespan).
// ---------------------------------------------------------------------------
#define AT_QH    0
#define AT_QL    16384
#define AT_KV    32768
#define AT_KVB   16384
#define AT_SMEM  (AT_KV + 2 * AT_KVB)   // 65536

__device__ __forceinline__ void attn_load_kv(
    const char* kh, const char* vh, uint32_t buf, int tid)
{
    #pragma unroll
    for (int i = 0; i < 2; i++) {
        int idx = tid + i * 256;          // 0..511
        int r   = idx >> 3;               // 0..63
        int cb  = (idx & 7) * 16;
        uint32_t so = swz((uint32_t)(r * 128 + cb));
        int go = r * 128 + cb;
        CP_ASYNC16(buf + so,         kh + go);
        CP_ASYNC16(buf + 8192 + so,  vh + go);
    }
}

__global__ __launch_bounds__(256) void attn_mma_kernel(
    const __half* __restrict__ Qh, const __half* __restrict__ Ql,
    const __half* __restrict__ Kh, const __half* __restrict__ Vh,
    __half* __restrict__ Ohi, __half* __restrict__ Olo)
{
    extern __shared__ char smem[];
    const uint32_t sb = smem_u32(smem);
    const int tid = threadIdx.x;
    const int w   = tid >> 5;
    const int lid = tid & 31;
    const int qt  = (int)(gridDim.z - 1 - blockIdx.z);   // LPT: heavy first
    const int q0  = qt * 128;
    const int h   = blockIdx.x;
    const int b   = blockIdx.y;

    const size_t headbase = ((size_t)(b * NHEAD + h)) * TSEQ * HDIM;
    const char* qh_g = (const char*)(Qh + headbase + (size_t)q0 * HDIM);
    const char* ql_g = (const char*)(Ql + headbase + (size_t)q0 * HDIM);
    const char* kh_g = (const char*)(Kh + headbase);
    const char* vh_g = (const char*)(Vh + headbase);

    #pragma unroll
    for (int i = 0; i < 4; i++) {
        int idx = tid + i * 256;
        int r   = idx >> 3;
        int cb  = (idx & 7) * 16;
        uint32_t so = swz((uint32_t)(r * 128 + cb));
        int go = r * 128 + cb;
        CP_ASYNC16(sb + AT_QH + so, qh_g + go);
        CP_ASYNC16(sb + AT_QL + so, ql_g + go);
    }
    attn_load_kv(kh_g, vh_g, sb + AT_KV, tid);
    CP_COMMIT();
    CP_WAIT0();
    __syncthreads();

    uint32_t aqh[4][4], aql[4][4];
    {
        uint32_t abase = (uint32_t)((w * 16 + (lid & 15)) * 128 + ((lid >> 4) << 4));
        #pragma unroll
        for (int ks = 0; ks < 4; ks++) {
            uint32_t ao = swz(abase + ks * 32);
            LDSM_X4(aqh[ks][0], aqh[ks][1], aqh[ks][2], aqh[ks][3], sb + AT_QH + ao);
            LDSM_X4(aql[ks][0], aql[ks][1], aql[ks][2], aql[ks][3], sb + AT_QL + ao);
        }
    }

    float o[8][4];
    #pragma unroll
    for (int j = 0; j < 8; j++)
        #pragma unroll
        for (int e = 0; e < 4; e++) o[j][e] = 0.0f;
    float m0 = -1e30f, m1 = -1e30f, l0 = 0.0f, l1 = 0.0f;

    const int row0 = q0 + w * 16 + (lid >> 2);
    const int row1 = row0 + 8;
    const uint32_t kbob = (uint32_t)((((lid >> 4) << 3) + (lid & 7)) * 128
                                     + (((lid >> 3) & 1) << 4));
    const uint32_t vbob = (uint32_t)(((lid & 7) + (((lid >> 3) & 1) << 3)) * 128
                                     + ((lid >> 4) << 4));

    const int nk = 2 * qt + 2;
    for (int kt = 0; kt < nk; kt++) {
        const uint32_t buf = sb + AT_KV + (kt & 1) * AT_KVB;
        if (kt + 1 < nk) {
            int ko = (kt + 1) * 64 * 128;
            attn_load_kv(kh_g + ko, vh_g + ko,
                         sb + AT_KV + ((kt + 1) & 1) * AT_KVB, tid);
            CP_COMMIT();
        }

        // ---- S = Q @ K^T (2-term: Qh*K + Ql*K) ----
        float s[8][4];
        #pragma unroll
        for (int j = 0; j < 8; j++)
            #pragma unroll
            for (int e = 0; e < 4; e++) s[j][e] = 0.0f;

        const uint32_t Kh_b = buf;
        #pragma unroll
        for (int ks = 0; ks < 4; ks++) {
            #pragma unroll
            for (int jg = 0; jg < 4; jg++) {
                uint32_t bo = swz(kbob + (uint32_t)(jg * 2048 + ks * 32));
                uint32_t k0r, k1r, k2r, k3r;
                LDSM_X4(k0r, k1r, k2r, k3r, Kh_b + bo);
                const int j0 = jg * 2, j1 = jg * 2 + 1;
                mma16816(s[j0], aqh[ks], k0r, k1r);
                mma16816(s[j1], aqh[ks], k2r, k3r);
                mma16816(s[j0], aql[ks], k0r, k1r);
                mma16816(s[j1], aql[ks], k2r, k3r);
            }
        }

        // ---- causal mask (boundary tiles only) ----
        if (kt * 64 + 63 > q0 + w * 16) {
            const int kc0 = kt * 64 + 2 * (lid & 3);
            #pragma unroll
            for (int j = 0; j < 8; j++) {
                int col = kc0 + 8 * j;
                if (col     > row0) s[j][0] = -1e30f;
                if (col + 1 > row0) s[j][1] = -1e30f;
                if (col     > row1) s[j][2] = -1e30f;
                if (col + 1 > row1) s[j][3] = -1e30f;
            }
        }

        // ---- online softmax ----
        float mx0 = -1e30f, mx1 = -1e30f;
        #pragma unroll
        for (int j = 0; j < 8; j++) {
            mx0 = fmaxf(mx0, fmaxf(s[j][0], s[j][1]));
            mx1 = fmaxf(mx1, fmaxf(s[j][2], s[j][3]));
        }
        mx0 = fmaxf(mx0, __shfl_xor_sync(0xffffffffu, mx0, 1));
        mx0 = fmaxf(mx0, __shfl_xor_sync(0xffffffffu, mx0, 2));
        mx1 = fmaxf(mx1, __shfl_xor_sync(0xffffffffu, mx1, 1));
        mx1 = fmaxf(mx1, __shfl_xor_sync(0xffffffffu, mx1, 2));
        float mn0 = fmaxf(m0, mx0), mn1 = fmaxf(m1, mx1);
        float corr0 = __expf(m0 - mn0), corr1 = __expf(m1 - mn1);
        m0 = mn0; m1 = mn1;
        float rs0 = 0.0f, rs1 = 0.0f;
        #pragma unroll
        for (int j = 0; j < 8; j++) {
            s[j][0] = __expf(s[j][0] - mn0);
            s[j][1] = __expf(s[j][1] - mn0);
            s[j][2] = __expf(s[j][2] - mn1);
            s[j][3] = __expf(s[j][3] - mn1);
            rs0 += s[j][0] + s[j][1];
            rs1 += s[j][2] + s[j][3];
        }
        rs0 += __shfl_xor_sync(0xffffffffu, rs0, 1);
        rs0 += __shfl_xor_sync(0xffffffffu, rs0, 2);
        rs1 += __shfl_xor_sync(0xffffffffu, rs1, 1);
        rs1 += __shfl_xor_sync(0xffffffffu, rs1, 2);
        l0 = l0 * corr0 + rs0;
        l1 = l1 * corr1 + rs1;
        #pragma unroll
        for (int j = 0; j < 8; j++) {
            o[j][0] *= corr0; o[j][1] *= corr0;
            o[j][2] *= corr1; o[j][3] *= corr1;
        }

        // ---- pack P into split fp16 A-fragments ----
        uint32_t ph[4][4], pl[4][4];
        #pragma unroll
        for (int ks = 0; ks < 4; ks++) {
            const int t0 = 2 * ks, t1 = 2 * ks + 1;
            split2h(s[t0][0], s[t0][1], ph[ks][0], pl[ks][0]);
            split2h(s[t0][2], s[t0][3], ph[ks][1], pl[ks][1]);
            split2h(s[t1][0], s[t1][1], ph[ks][2], pl[ks][2]);
            split2h(s[t1][2], s[t1][3], ph[ks][3], pl[ks][3]);
        }

        // ---- O += P @ V (2-term: Ph*V + Pl*V) ----
        const uint32_t Vh_b = buf + 8192;
        #pragma unroll
        for (int ks = 0; ks < 4; ks++) {
            #pragma unroll
            for (int dg = 0; dg < 4; dg++) {
                uint32_t vo = swz(vbob + (uint32_t)(ks * 16 * 128 + dg * 32));
                uint32_t v0, v1, v2, v3;
                LDSM_X4_T(v0, v1, v2, v3, Vh_b + vo);
                const int d0 = dg * 2, d1 = dg * 2 + 1;
                mma16816(o[d0], ph[ks], v0, v1);
                mma16816(o[d1], ph[ks], v2, v3);
                mma16816(o[d0], pl[ks], v0, v1);
                mma16816(o[d1], pl[ks], v2, v3);
            }
        }

        if (kt + 1 < nk) {
            CP_WAIT0();
            __syncthreads();
        }
    }

    // ---- epilogue: normalize, split to fp16 hi/lo, write [t][h*64+d] ----
    const float inv0 = 1.0f / l0;
    const float inv1 = 1.0f / l1;
    const size_t ro0 = ((size_t)(b * TSEQ) + row0) * EMBED + h * HDIM;
    const size_t ro1 = ((size_t)(b * TSEQ) + row1) * EMBED + h * HDIM;
    #pragma unroll
    for (int j = 0; j < 8; j++) {
        const int col = 8 * j + 2 * (lid & 3);
        uint32_t H, L;
        split2h(o[j][0] * inv0, o[j][1] * inv0, H, L);
        *(uint32_t*)(Ohi + ro0 + col) = H;
        *(uint32_t*)(Olo + ro0 + col) = L;
        split2h(o[j][2] * inv1, o[j][3] * inv1, H, L);
        *(uint32_t*)(Ohi + ro1 + col) = H;
        *(uint32_t*)(Olo + ro1 + col) = L;
    }
}

// ---------------------------------------------------------------------------
// Launch
// ---------------------------------------------------------------------------
extern "C" void kernel_launch(void* const* d_in, const int* in_sizes, int n_in,
                              void* d_out, int out_size)
{
    const float* x     = (const float*)d_in[0];
    const float* w_qkv = (const float*)d_in[1];
    const float* b_qkv = (const float*)d_in[2];
    const float* w_out = (const float*)d_in[3];
    const float* b_out = (const float*)d_in[4];
    float* out = (float*)d_out;

    __half *xa_hi, *xa_lo, *wq, *wo, *qh, *ql, *kh, *vh;
    cudaGetSymbolAddress((void**)&xa_hi, g_xa_hi);
    cudaGetSymbolAddress((void**)&xa_lo, g_xa_lo);
    cudaGetSymbolAddress((void**)&wq, g_wq);
    cudaGetSymbolAddress((void**)&wo, g_wo);
    cudaGetSymbolAddress((void**)&qh, g_qh);
    cudaGetSymbolAddress((void**)&ql, g_ql);
    cudaGetSymbolAddress((void**)&kh, g_kh);
    cudaGetSymbolAddress((void**)&vh, g_vh);

    cudaFuncSetAttribute(gemm_mma_kernel<0>,
                         cudaFuncAttributeMaxDynamicSharedMemorySize, GEMM_SMEM);
    cudaFuncSetAttribute(gemm_mma_kernel<1>,
                         cudaFuncAttributeMaxDynamicSharedMemorySize, GEMM_SMEM);
    cudaFuncSetAttribute(attn_mma_kernel,
                         cudaFuncAttributeMaxDynamicSharedMemorySize, AT_SMEM);

    // 1) fused prep: split x + convert both weight matrices (one launch)
    prep_kernel<<<PREP_BLOCKS, 256>>>(x, w_qkv, w_out, xa_hi, xa_lo, wq, wo);

    // 2) QKV projection (tensor cores) -> fused per-head epilogue
    {
        dim3 grid(QKVCOLS / 128, MTOK / 128);
        gemm_mma_kernel<1><<<grid, 256, GEMM_SMEM>>>(
            xa_hi, xa_lo, wq, b_qkv, nullptr, QKVCOLS, qh, ql, kh, vh);
    }

    // 3) tensor-core flash attention (LPT grid: qt on z, reversed)
    {
        dim3 grid(NHEAD, BATCH, TSEQ / 128);
        attn_mma_kernel<<<grid, 256, AT_SMEM>>>(qh, ql, kh, vh, xa_hi, xa_lo);
    }

    // 4) output projection (tensor cores)
    {
        dim3 grid(EMBED / 128, MTOK / 128);
        gemm_mma_kernel<0><<<grid, 256, GEMM_SMEM>>>(
            xa_hi, xa_lo, wo, b_out, out, EMBED,
            nullptr, nullptr, nullptr, nullptr);
    }
}

// round 16
// speedup vs baseline: 1.3893x; 1.3893x over previous
#include <cuda_runtime.h>
#include <cuda_fp16.h>
#include <cstdint>
#include <math.h>

// Problem constants
#define BATCH   2
#define TSEQ    2048
#define EMBED   1024
#define NHEAD   16
#define HDIM    64
#define MTOK    (BATCH * TSEQ)        // 4096
#define QKVCOLS (3 * EMBED)           // 3072

// Scratch (allocation-free rule: __device__ globals)
__device__ __half g_xa_hi[(size_t)MTOK * EMBED];    // x split / attn out split (hi)
__device__ __half g_xa_lo[(size_t)MTOK * EMBED];    // (lo)
__device__ __half g_wq[(size_t)QKVCOLS * EMBED];    // w_qkv^T [3072][1024] fp16
__device__ __half g_wo[(size_t)EMBED * EMBED];      // w_out^T [1024][1024] fp16
// per-head qkv: [b][h][t][64]
__device__ __half g_qh[(size_t)MTOK * EMBED];
__device__ __half g_ql[(size_t)MTOK * EMBED];
__device__ __half g_kh[(size_t)MTOK * EMBED];
__device__ __half g_vh[(size_t)MTOK * EMBED];

// ---------------------------------------------------------------------------
// PTX helpers (plain sm_80+ PTX)
// ---------------------------------------------------------------------------
__device__ __forceinline__ uint32_t smem_u32(const void* p) {
    uint32_t a;
    asm("{ .reg .u64 t; cvta.to.shared.u64 t, %1; cvt.u32.u64 %0, t; }"
        : "=r"(a) : "l"(p));
    return a;
}

#define CP_ASYNC16(dst, src) \
    asm volatile("cp.async.cg.shared.global [%0], [%1], 16;" :: "r"(dst), "l"(src))
#define CP_COMMIT()  asm volatile("cp.async.commit_group;" ::: "memory")
#define CP_WAIT0()   asm volatile("cp.async.wait_group 0;" ::: "memory")

#define LDSM_X4(r0, r1, r2, r3, a) \
    asm volatile("ldmatrix.sync.aligned.m8n8.x4.shared.b16 {%0,%1,%2,%3}, [%4];" \
                 : "=r"(r0), "=r"(r1), "=r"(r2), "=r"(r3) : "r"(a))
#define LDSM_X4_T(r0, r1, r2, r3, a) \
    asm volatile("ldmatrix.sync.aligned.m8n8.x4.trans.shared.b16 {%0,%1,%2,%3}, [%4];" \
                 : "=r"(r0), "=r"(r1), "=r"(r2), "=r"(r3) : "r"(a))

__device__ __forceinline__ void mma16816(float* d, const uint32_t* a,
                                         uint32_t b0, uint32_t b1) {
    asm volatile(
        "mma.sync.aligned.m16n8k16.row.col.f32.f16.f16.f32 "
        "{%0,%1,%2,%3}, {%4,%5,%6,%7}, {%8,%9}, {%0,%1,%2,%3};"
        : "+f"(d[0]), "+f"(d[1]), "+f"(d[2]), "+f"(d[3])
        : "r"(a[0]), "r"(a[1]), "r"(a[2]), "r"(a[3]), "r"(b0), "r"(b1));
}

__device__ __forceinline__ uint32_t swz(uint32_t o) {
    return o ^ ((o >> 3) & 0x70);
}

// Split pair of floats into packed fp16 hi + fp16 lo residual
__device__ __forceinline__ void split2h(float a, float b, uint32_t& h, uint32_t& l) {
    __half ha = __float2half(a), hb = __float2half(b);
    float ra = a - __half2float(ha);
    float rb = b - __half2float(hb);
    __half2 H = __halves2half2(ha, hb);
    __half2 L = __halves2half2(__float2half(ra), __float2half(rb));
    h = *(uint32_t*)&H;
    l = *(uint32_t*)&L;
}
// Pack pair of floats to fp16x2 (round-to-nearest)
__device__ __forceinline__ uint32_t pack2h(float a, float b) {
    __half2 H = __halves2half2(__float2half(a), __float2half(b));
    return *(uint32_t*)&H;
}

// ---------------------------------------------------------------------------
// Fused prep (single launch, 3 sections):
//  [0, 4096)       : split x fp32 -> fp16 hi/lo
//  [4096, 7168)    : transpose+convert w_qkv -> [3072][1024] fp16
//  [7168, 8192)    : transpose+convert w_out -> [1024][1024] fp16
// ---------------------------------------------------------------------------
#define PREP_SPLIT_BLOCKS 4096
#define PREP_WQ_BLOCKS    3072
#define PREP_WO_BLOCKS    1024
#define PREP_BLOCKS (PREP_SPLIT_BLOCKS + PREP_WQ_BLOCKS + PREP_WO_BLOCKS)

__device__ __forceinline__ void wconv_tile(
    const float* __restrict__ W, __half* __restrict__ T,
    int K, int N, int n0, int k0, int tid, float* t /*[32][33]*/)
{
    int tx = tid & 31, ty = tid >> 5;            // 32 x 8
    #pragma unroll
    for (int i = 0; i < 4; i++)
        t[(ty + i * 8) * 33 + tx] = W[(size_t)(k0 + ty + i * 8) * N + n0 + tx];
    __syncthreads();
    #pragma unroll
    for (int i = 0; i < 4; i++) {
        float v = t[tx * 33 + ty + i * 8];
        T[(size_t)(n0 + ty + i * 8) * K + k0 + tx] = __float2half(v);
    }
}

__global__ __launch_bounds__(256) void prep_kernel(
    const float* __restrict__ x, const float* __restrict__ w_qkv,
    const float* __restrict__ w_out,
    __half* __restrict__ xa_hi, __half* __restrict__ xa_lo,
    __half* __restrict__ wq, __half* __restrict__ wo)
{
    __shared__ float t[32 * 33];
    const int bid = blockIdx.x;
    const int tid = threadIdx.x;

    if (bid < PREP_SPLIT_BLOCKS) {
        int i = bid * 256 + tid;
        float4 v = ((const float4*)x)[i];
        uint32_t h0, l0, h1, l1;
        split2h(v.x, v.y, h0, l0);
        split2h(v.z, v.w, h1, l1);
        uint32_t* hp = (uint32_t*)xa_hi;
        uint32_t* lp = (uint32_t*)xa_lo;
        hp[2*i] = h0; hp[2*i+1] = h1;
        lp[2*i] = l0; lp[2*i+1] = l1;
    } else if (bid < PREP_SPLIT_BLOCKS + PREP_WQ_BLOCKS) {
        int b2 = bid - PREP_SPLIT_BLOCKS;
        int n0 = (b2 % 96) * 32;
        int k0 = (b2 / 96) * 32;
        wconv_tile(w_qkv, wq, EMBED, QKVCOLS, n0, k0, tid, t);
    } else {
        int b2 = bid - PREP_SPLIT_BLOCKS - PREP_WQ_BLOCKS;
        int n0 = (b2 % 32) * 32;
        int k0 = (b2 / 32) * 32;
        wconv_tile(w_out, wo, EMBED, EMBED, n0, k0, tid, t);
    }
}

// ---------------------------------------------------------------------------
// Warp-mma GEMM (fp16 2-term): C = (Ahi+Alo)[M,1024] @ (B[N,1024])^T + bias
// 128x128 CTA tile, 256 threads = 8 warps (4m x 2n), 32x64 per warp.
// K chunk = 64 fp16, double-buffered cp.async (96KB smem -> 2 CTAs/SM).
// MODE 0: fp32 C output.  MODE 1: QKV epilogue (scale+split q; fp16 k, v)
// ---------------------------------------------------------------------------
#define GK      1024
#define NCHUNK  16
#define TILE_B  16384
#define BUF_B   (3 * TILE_B)        // Ah, Al, Bh
#define GEMM_SMEM (2 * BUF_B)       // 98304

__device__ __forceinline__ void load_chunk_async(
    const __half* __restrict__ Ahi, const __half* __restrict__ Alo,
    const __half* __restrict__ Bh,
    int bm, int bn, int kbyte, uint32_t buf, int tid)
{
    #pragma unroll
    for (int i = 0; i < 4; i++) {
        int idx = tid + i * 256;                  // 0..1023
        int r   = idx >> 3;                       // 0..127
        int cb  = (idx & 7) * 16;
        uint32_t so = swz((uint32_t)(r * 128 + cb));
        const char* gA = (const char*)(Ahi + (size_t)(bm + r) * GK) + kbyte + cb;
        const char* gAl= (const char*)(Alo + (size_t)(bm + r) * GK) + kbyte + cb;
        const char* gB = (const char*)(Bh  + (size_t)(bn + r) * GK) + kbyte + cb;
        CP_ASYNC16(buf + so,              gA);
        CP_ASYNC16(buf + TILE_B + so,     gAl);
        CP_ASYNC16(buf + 2 * TILE_B + so, gB);
    }
}

template <int MODE>
__global__ __launch_bounds__(256, 2) void gemm_mma_kernel(
    const __half* __restrict__ Ahi, const __half* __restrict__ Alo,
    const __half* __restrict__ Bh,
    const float* __restrict__ bias, float* __restrict__ C, int N,
    __half* __restrict__ qh, __half* __restrict__ ql,
    __half* __restrict__ kh, __half* __restrict__ vh)
{
    extern __shared__ char smem[];
    const uint32_t sb = smem_u32(smem);
    const int tid = threadIdx.x;
    const int wid = tid >> 5;
    const int lid = tid & 31;
    const int wm  = wid >> 1;       // 0..3 -> m offset wm*32
    const int wn  = wid & 1;        // 0..1 -> n offset wn*64

    const int bm = blockIdx.y * 128;
    const int bn = blockIdx.x * 128;

    float acc[2][8][4];
    #pragma unroll
    for (int a = 0; a < 2; a++)
        #pragma unroll
        for (int j = 0; j < 8; j++)
            #pragma unroll
            for (int k = 0; k < 4; k++) acc[a][j][k] = 0.0f;

    uint32_t aob[2];
    #pragma unroll
    for (int mf = 0; mf < 2; mf++)
        aob[mf] = (uint32_t)((wm * 32 + mf * 16 + (lid & 15)) * 128 + ((lid >> 4) << 4));
    uint32_t bob = (uint32_t)((wn * 64 + ((lid >> 4) << 3) + (lid & 7)) * 128
                              + (((lid >> 3) & 1) << 4));

    load_chunk_async(Ahi, Alo, Bh, bm, bn, 0, sb, tid);
    CP_COMMIT();
    CP_WAIT0();
    __syncthreads();

    for (int c = 0; c < NCHUNK; c++) {
        const uint32_t buf = sb + (c & 1) * BUF_B;
        if (c + 1 < NCHUNK) {
            load_chunk_async(Ahi, Alo, Bh, bm, bn, (c + 1) * 128,
                             sb + ((c + 1) & 1) * BUF_B, tid);
            CP_COMMIT();
        }

        const uint32_t Ah_b = buf;
        const uint32_t Al_b = buf + TILE_B;
        const uint32_t Bh_b = buf + 2 * TILE_B;

        #pragma unroll
        for (int ks = 0; ks < 4; ks++) {
            const uint32_t ko = (uint32_t)(ks * 32);
            uint32_t ah[2][4], al[2][4];
            #pragma unroll
            for (int mf = 0; mf < 2; mf++) {
                uint32_t ao = swz(aob[mf] + ko);
                LDSM_X4(ah[mf][0], ah[mf][1], ah[mf][2], ah[mf][3], Ah_b + ao);
                LDSM_X4(al[mf][0], al[mf][1], al[mf][2], al[mf][3], Al_b + ao);
            }
            #pragma unroll
            for (int jg = 0; jg < 4; jg++) {
                uint32_t bo = swz(bob + (uint32_t)(jg * 2048) + ko);
                uint32_t b0, b1, b2, b3;
                LDSM_X4(b0, b1, b2, b3, Bh_b + bo);
                const int j0 = jg * 2, j1 = jg * 2 + 1;
                #pragma unroll
                for (int mf = 0; mf < 2; mf++) {
                    mma16816(acc[mf][j0], ah[mf], b0, b1);
                    mma16816(acc[mf][j1], ah[mf], b2, b3);
                    mma16816(acc[mf][j0], al[mf], b0, b1);
                    mma16816(acc[mf][j1], al[mf], b2, b3);
                }
            }
        }

        if (c + 1 < NCHUNK) {
            CP_WAIT0();
            __syncthreads();
        }
    }

    const int rbase = bm + wm * 32 + (lid >> 2);
    const int cbase = bn + wn * 64 + (lid & 3) * 2;

    if (MODE == 0) {
        #pragma unroll
        for (int j = 0; j < 8; j++) {
            const int col = cbase + j * 8;
            float2 bb = *(const float2*)&bias[col];
            #pragma unroll
            for (int mf = 0; mf < 2; mf++) {
                int r0 = rbase + mf * 16;
                float2 v0, v1;
                v0.x = acc[mf][j][0] + bb.x;
                v0.y = acc[mf][j][1] + bb.y;
                v1.x = acc[mf][j][2] + bb.x;
                v1.y = acc[mf][j][3] + bb.y;
                *(float2*)&C[(size_t)r0 * N + col]       = v0;
                *(float2*)&C[(size_t)(r0 + 8) * N + col] = v1;
            }
        }
    } else {
        // QKV epilogue: bias; q scaled 0.125 + split hi/lo; k,v single fp16
        #pragma unroll
        for (int j = 0; j < 8; j++) {
            const int col = cbase + j * 8;
            float2 bb = *(const float2*)&bias[col];
            const int sec = col >> 10;
            const int rr  = col & 1023;
            const int hh  = rr >> 6;
            const int dd  = rr & 63;
            #pragma unroll
            for (int mf = 0; mf < 2; mf++) {
                #pragma unroll
                for (int half = 0; half < 2; half++) {
                    int row = rbase + mf * 16 + half * 8;
                    float a0 = acc[mf][j][half*2+0] + bb.x;
                    float a1 = acc[mf][j][half*2+1] + bb.y;
                    int bb_ = row >> 11, tt = row & 2047;
                    size_t off = (((size_t)(bb_ * NHEAD + hh)) * TSEQ + tt) * HDIM + dd;
                    if (sec == 0) {
                        uint32_t H, L;
                        split2h(a0 * 0.125f, a1 * 0.125f, H, L);
                        *(uint32_t*)(qh + off) = H;
                        *(uint32_t*)(ql + off) = L;
                    } else if (sec == 1) {
                        *(uint32_t*)(kh + off) = pack2h(a0, a1);
                    } else {
                        *(uint32_t*)(vh + off) = pack2h(a0, a1);
                    }
                }
            }
        }
    }
}

// ---------------------------------------------------------------------------
// Tensor-core flash attention (fp16 2-term, causal) — R13 grid:
// grid (TSEQ/128, NHEAD, BATCH), qt = blockIdx.x (natural launch order).
// ---------------------------------------------------------------------------
#define AT_QH    0
#define AT_QL    16384
#define AT_KV    32768
#define AT_KVB   16384
#define AT_SMEM  (AT_KV + 2 * AT_KVB)   // 65536

__device__ __forceinline__ void attn_load_kv(
    const char* kh, const char* vh, uint32_t buf, int tid)
{
    #pragma unroll
    for (int i = 0; i < 2; i++) {
        int idx = tid + i * 256;          // 0..511
        int r   = idx >> 3;               // 0..63
        int cb  = (idx & 7) * 16;
        uint32_t so = swz((uint32_t)(r * 128 + cb));
        int go = r * 128 + cb;
        CP_ASYNC16(buf + so,         kh + go);
        CP_ASYNC16(buf + 8192 + so,  vh + go);
    }
}

__global__ __launch_bounds__(256) void attn_mma_kernel(
    const __half* __restrict__ Qh, const __half* __restrict__ Ql,
    const __half* __restrict__ Kh, const __half* __restrict__ Vh,
    __half* __restrict__ Ohi, __half* __restrict__ Olo)
{
    extern __shared__ char smem[];
    const uint32_t sb = smem_u32(smem);
    const int tid = threadIdx.x;
    const int w   = tid >> 5;
    const int lid = tid & 31;
    const int qt  = blockIdx.x;
    const int q0  = qt * 128;
    const int h   = blockIdx.y;
    const int b   = blockIdx.z;

    const size_t headbase = ((size_t)(b * NHEAD + h)) * TSEQ * HDIM;
    const char* qh_g = (const char*)(Qh + headbase + (size_t)q0 * HDIM);
    const char* ql_g = (const char*)(Ql + headbase + (size_t)q0 * HDIM);
    const char* kh_g = (const char*)(Kh + headbase);
    const char* vh_g = (const char*)(Vh + headbase);

    #pragma unroll
    for (int i = 0; i < 4; i++) {
        int idx = tid + i * 256;
        int r   = idx >> 3;
        int cb  = (idx & 7) * 16;
        uint32_t so = swz((uint32_t)(r * 128 + cb));
        int go = r * 128 + cb;
        CP_ASYNC16(sb + AT_QH + so, qh_g + go);
        CP_ASYNC16(sb + AT_QL + so, ql_g + go);
    }
    attn_load_kv(kh_g, vh_g, sb + AT_KV, tid);
    CP_COMMIT();
    CP_WAIT0();
    __syncthreads();

    uint32_t aqh[4][4], aql[4][4];
    {
        uint32_t abase = (uint32_t)((w * 16 + (lid & 15)) * 128 + ((lid >> 4) << 4));
        #pragma unroll
        for (int ks = 0; ks < 4; ks++) {
            uint32_t ao = swz(abase + ks * 32);
            LDSM_X4(aqh[ks][0], aqh[ks][1], aqh[ks][2], aqh[ks][3], sb + AT_QH + ao);
            LDSM_X4(aql[ks][0], aql[ks][1], aql[ks][2], aql[ks][3], sb + AT_QL + ao);
        }
    }

    float o[8][4];
    #pragma unroll
    for (int j = 0; j < 8; j++)
        #pragma unroll
        for (int e = 0; e < 4; e++) o[j][e] = 0.0f;
    float m0 = -1e30f, m1 = -1e30f, l0 = 0.0f, l1 = 0.0f;

    const int row0 = q0 + w * 16 + (lid >> 2);
    const int row1 = row0 + 8;
    const uint32_t kbob = (uint32_t)((((lid >> 4) << 3) + (lid & 7)) * 128
                                     + (((lid >> 3) & 1) << 4));
    const uint32_t vbob = (uint32_t)(((lid & 7) + (((lid >> 3) & 1) << 3)) * 128
                                     + ((lid >> 4) << 4));

    const int nk = 2 * qt + 2;
    for (int kt = 0; kt < nk; kt++) {
        const uint32_t buf = sb + AT_KV + (kt & 1) * AT_KVB;
        if (kt + 1 < nk) {
            int ko = (kt + 1) * 64 * 128;
            attn_load_kv(kh_g + ko, vh_g + ko,
                         sb + AT_KV + ((kt + 1) & 1) * AT_KVB, tid);
            CP_COMMIT();
        }

        // ---- S = Q @ K^T (2-term: Qh*K + Ql*K) ----
        float s[8][4];
        #pragma unroll
        for (int j = 0; j < 8; j++)
            #pragma unroll
            for (int e = 0; e < 4; e++) s[j][e] = 0.0f;

        const uint32_t Kh_b = buf;
        #pragma unroll
        for (int ks = 0; ks < 4; ks++) {
            #pragma unroll
            for (int jg = 0; jg < 4; jg++) {
                uint32_t bo = swz(kbob + (uint32_t)(jg * 2048 + ks * 32));
                uint32_t k0r, k1r, k2r, k3r;
                LDSM_X4(k0r, k1r, k2r, k3r, Kh_b + bo);
                const int j0 = jg * 2, j1 = jg * 2 + 1;
                mma16816(s[j0], aqh[ks], k0r, k1r);
                mma16816(s[j1], aqh[ks], k2r, k3r);
                mma16816(s[j0], aql[ks], k0r, k1r);
                mma16816(s[j1], aql[ks], k2r, k3r);
            }
        }

        // ---- causal mask (boundary tiles only) ----
        if (kt * 64 + 63 > q0 + w * 16) {
            const int kc0 = kt * 64 + 2 * (lid & 3);
            #pragma unroll
            for (int j = 0; j < 8; j++) {
                int col = kc0 + 8 * j;
                if (col     > row0) s[j][0] = -1e30f;
                if (col + 1 > row0) s[j][1] = -1e30f;
                if (col     > row1) s[j][2] = -1e30f;
                if (col + 1 > row1) s[j][3] = -1e30f;
            }
        }

        // ---- online softmax ----
        float mx0 = -1e30f, mx1 = -1e30f;
        #pragma unroll
        for (int j = 0; j < 8; j++) {
            mx0 = fmaxf(mx0, fmaxf(s[j][0], s[j][1]));
            mx1 = fmaxf(mx1, fmaxf(s[j][2], s[j][3]));
        }
        mx0 = fmaxf(mx0, __shfl_xor_sync(0xffffffffu, mx0, 1));
        mx0 = fmaxf(mx0, __shfl_xor_sync(0xffffffffu, mx0, 2));
        mx1 = fmaxf(mx1, __shfl_xor_sync(0xffffffffu, mx1, 1));
        mx1 = fmaxf(mx1, __shfl_xor_sync(0xffffffffu, mx1, 2));
        float mn0 = fmaxf(m0, mx0), mn1 = fmaxf(m1, mx1);
        float corr0 = __expf(m0 - mn0), corr1 = __expf(m1 - mn1);
        m0 = mn0; m1 = mn1;
        float rs0 = 0.0f, rs1 = 0.0f;
        #pragma unroll
        for (int j = 0; j < 8; j++) {
            s[j][0] = __expf(s[j][0] - mn0);
            s[j][1] = __expf(s[j][1] - mn0);
            s[j][2] = __expf(s[j][2] - mn1);
            s[j][3] = __expf(s[j][3] - mn1);
            rs0 += s[j][0] + s[j][1];
            rs1 += s[j][2] + s[j][3];
        }
        rs0 += __shfl_xor_sync(0xffffffffu, rs0, 1);
        rs0 += __shfl_xor_sync(0xffffffffu, rs0, 2);
        rs1 += __shfl_xor_sync(0xffffffffu, rs1, 1);
        rs1 += __shfl_xor_sync(0xffffffffu, rs1, 2);
        l0 = l0 * corr0 + rs0;
        l1 = l1 * corr1 + rs1;
        #pragma unroll
        for (int j = 0; j < 8; j++) {
            o[j][0] *= corr0; o[j][1] *= corr0;
            o[j][2] *= corr1; o[j][3] *= corr1;
        }

        // ---- pack P into split fp16 A-fragments ----
        uint32_t ph[4][4], pl[4][4];
        #pragma unroll
        for (int ks = 0; ks < 4; ks++) {
            const int t0 = 2 * ks, t1 = 2 * ks + 1;
            split2h(s[t0][0], s[t0][1], ph[ks][0], pl[ks][0]);
            split2h(s[t0][2], s[t0][3], ph[ks][1], pl[ks][1]);
            split2h(s[t1][0], s[t1][1], ph[ks][2], pl[ks][2]);
            split2h(s[t1][2], s[t1][3], ph[ks][3], pl[ks][3]);
        }

        // ---- O += P @ V (2-term: Ph*V + Pl*V) ----
        const uint32_t Vh_b = buf + 8192;
        #pragma unroll
        for (int ks = 0; ks < 4; ks++) {
            #pragma unroll
            for (int dg = 0; dg < 4; dg++) {
                uint32_t vo = swz(vbob + (uint32_t)(ks * 16 * 128 + dg * 32));
                uint32_t v0, v1, v2, v3;
                LDSM_X4_T(v0, v1, v2, v3, Vh_b + vo);
                const int d0 = dg * 2, d1 = dg * 2 + 1;
                mma16816(o[d0], ph[ks], v0, v1);
                mma16816(o[d1], ph[ks], v2, v3);
                mma16816(o[d0], pl[ks], v0, v1);
                mma16816(o[d1], pl[ks], v2, v3);
            }
        }

        if (kt + 1 < nk) {
            CP_WAIT0();
            __syncthreads();
        }
    }

    // ---- epilogue: normalize, split to fp16 hi/lo, write [t][h*64+d] ----
    const float inv0 = 1.0f / l0;
    const float inv1 = 1.0f / l1;
    const size_t ro0 = ((size_t)(b * TSEQ) + row0) * EMBED + h * HDIM;
    const size_t ro1 = ((size_t)(b * TSEQ) + row1) * EMBED + h * HDIM;
    #pragma unroll
    for (int j = 0; j < 8; j++) {
        const int col = 8 * j + 2 * (lid & 3);
        uint32_t H, L;
        split2h(o[j][0] * inv0, o[j][1] * inv0, H, L);
        *(uint32_t*)(Ohi + ro0 + col) = H;
        *(uint32_t*)(Olo + ro0 + col) = L;
        split2h(o[j][2] * inv1, o[j][3] * inv1, H, L);
        *(uint32_t*)(Ohi + ro1 + col) = H;
        *(uint32_t*)(Olo + ro1 + col) = L;
    }
}

// ---------------------------------------------------------------------------
// Launch
// ---------------------------------------------------------------------------
extern "C" void kernel_launch(void* const* d_in, const int* in_sizes, int n_in,
                              void* d_out, int out_size)
{
    const float* x     = (const float*)d_in[0];
    const float* w_qkv = (const float*)d_in[1];
    const float* b_qkv = (const float*)d_in[2];
    const float* w_out = (const float*)d_in[3];
    const float* b_out = (const float*)d_in[4];
    float* out = (float*)d_out;

    __half *xa_hi, *xa_lo, *wq, *wo, *qh, *ql, *kh, *vh;
    cudaGetSymbolAddress((void**)&xa_hi, g_xa_hi);
    cudaGetSymbolAddress((void**)&xa_lo, g_xa_lo);
    cudaGetSymbolAddress((void**)&wq, g_wq);
    cudaGetSymbolAddress((void**)&wo, g_wo);
    cudaGetSymbolAddress((void**)&qh, g_qh);
    cudaGetSymbolAddress((void**)&ql, g_ql);
    cudaGetSymbolAddress((void**)&kh, g_kh);
    cudaGetSymbolAddress((void**)&vh, g_vh);

    cudaFuncSetAttribute(gemm_mma_kernel<0>,
                         cudaFuncAttributeMaxDynamicSharedMemorySize, GEMM_SMEM);
    cudaFuncSetAttribute(gemm_mma_kernel<1>,
                         cudaFuncAttributeMaxDynamicSharedMemorySize, GEMM_SMEM);
    cudaFuncSetAttribute(attn_mma_kernel,
                         cudaFuncAttributeMaxDynamicSharedMemorySize, AT_SMEM);

    // 1) fused prep: split x + convert both weight matrices (one launch)
    prep_kernel<<<PREP_BLOCKS, 256>>>(x, w_qkv, w_out, xa_hi, xa_lo, wq, wo);

    // 2) QKV projection (tensor cores) -> fused per-head epilogue
    {
        dim3 grid(QKVCOLS / 128, MTOK / 128);
        gemm_mma_kernel<1><<<grid, 256, GEMM_SMEM>>>(
            xa_hi, xa_lo, wq, b_qkv, nullptr, QKVCOLS, qh, ql, kh, vh);
    }

    // 3) tensor-core flash attention (R13 grid: qt on x, natural order)
    {
        dim3 grid(TSEQ / 128, NHEAD, BATCH);
        attn_mma_kernel<<<grid, 256, AT_SMEM>>>(qh, ql, kh, vh, xa_hi, xa_lo);
    }

    // 4) output projection (tensor cores)
    {
        dim3 grid(EMBED / 128, MTOK / 128);
        gemm_mma_kernel<0><<<grid, 256, GEMM_SMEM>>>(
            xa_hi, xa_lo, wo, b_out, out, EMBED,
            nullptr, nullptr, nullptr, nullptr);
    }
}